// round 1
// baseline (speedup 1.0000x reference)
#include <cuda_runtime.h>

#define TINYF 1.1920928955078125e-07f  // np.finfo(float32).eps

__device__ __forceinline__ float cround1(float x) {
    // floor(x - sign(x)*tiny + 0.5); copysign matches sign() for all x incl. +-0 here
    float s = copysignf(TINYF, x);
    return floorf((x - s) + 0.5f);
}

// One coset step of the D8 closest-point algorithm:
// f = round(x); if sum(f) odd, flip the coordinate with max |x - f|
// using the reference's exact tie rules. Writes candidate y.
__device__ __forceinline__ void coset_flip(const float xv[8], float y[8]) {
    float f[8], e[8];
#pragma unroll
    for (int i = 0; i < 8; i++) {
        f[i] = cround1(xv[i]);
        e[i] = xv[i] - f[i];
    }
    float sum = ((f[0] + f[1]) + (f[2] + f[3])) + ((f[4] + f[5]) + (f[6] + f[7]));
    int odd = ((int)sum) & 1;  // sum is an exact small integer

    // first-index argmax of |e| (strict > keeps the first max, like jnp.argmax)
    float bd = fabsf(e[0]);
    float be = e[0];
    float bx = xv[0];
    int bk = 0;
#pragma unroll
    for (int i = 1; i < 8; i++) {
        float di = fabsf(e[i]);
        bool g = di > bd;
        bd = g ? di : bd;
        be = g ? e[i] : be;
        bx = g ? xv[i] : bx;
        bk = g ? i : bk;
    }
    // step = where(xk>=0, where(fk<xk,1,-1), where(fk<=xk,1,-1));
    // fk<xk <=> e>0, fk<=xk <=> e>=0
    float step = (bx >= 0.f) ? ((be > 0.f) ? 1.f : -1.f)
                             : ((be >= 0.f) ? 1.f : -1.f);
    int kk = odd ? bk : 8;  // 8 = no flip
#pragma unroll
    for (int i = 0; i < 8; i++)
        y[i] = (i == kk) ? (f[i] + step) : f[i];
}

// E8 = D8  U  (D8 + 1/2)
__device__ __forceinline__ void closest_E8(const float xv[8], float y[8]) {
    float y0[8], y1[8], xs[8];
    coset_flip(xv, y0);
#pragma unroll
    for (int i = 0; i < 8; i++) xs[i] = xv[i] - 0.5f;
    coset_flip(xs, y1);
#pragma unroll
    for (int i = 0; i < 8; i++) y1[i] += 0.5f;

    float d0 = 0.f, d1 = 0.f;
#pragma unroll
    for (int i = 0; i < 8; i++) {
        float t0 = xv[i] - y0[i];
        d0 = fmaf(t0, t0, d0);
        float t1 = xv[i] - y1[i];
        d1 = fmaf(t1, t1, d1);
    }
    bool c = d0 < d1;  // ties pick y1, matching jnp.where(d0 < d1, y0, y1)
#pragma unroll
    for (int i = 0; i < 8; i++) y[i] = c ? y0[i] : y1[i];
}

__global__ __launch_bounds__(256, 2)
void LatticeQuantizer_kernel(const float* __restrict__ x,
                             const float* __restrict__ betap,
                             const float* __restrict__ epsp,
                             float* __restrict__ out, int N) {
    int r = blockIdx.x * blockDim.x + threadIdx.x;
    if (r >= N) return;

    const float4* x4 = reinterpret_cast<const float4*>(x);
    float4 a = x4[2 * r];
    float4 bb = x4[2 * r + 1];

    float beta = __ldg(betap);
    float ib = 1.0f / beta;  // beta == 1 in this problem -> exact

    float4 e0 = __ldg(reinterpret_cast<const float4*>(epsp));
    float4 e1 = __ldg(reinterpret_cast<const float4*>(epsp) + 1);
    float ep[8] = {e0.x, e0.y, e0.z, e0.w, e1.x, e1.y, e1.z, e1.w};

    float xl[8] = {a.x * ib, a.y * ib, a.z * ib, a.w * ib,
                   bb.x * ib, bb.y * ib, bb.z * ib, bb.w * ib};

    // ------------------- encode: M=3 hierarchical layers -------------------
    float bq[3][8];
#pragma unroll
    for (int m = 0; m < 3; m++) {
        float tin[8], cp[8];
#pragma unroll
        for (int i = 0; i < 8; i++) tin[i] = xl[i] + ep[i];
        closest_E8(tin, cp);

        // z = cp @ G_inv  via exact forward solve against sparse 'rows'
        float z[8];
        z[0] = 0.5f * cp[0];
#pragma unroll
        for (int i = 1; i < 7; i++) z[i] = cp[i] + z[i - 1];
        float s06 = ((z[0] + z[1]) + (z[2] + z[3])) + ((z[4] + z[5]) + z[6]);
        z[7] = fmaf(2.f, cp[7], -s06);

        // b = custom_round(fmod(z, 4))  (exact dyadic decomposition of fmod)
#pragma unroll
        for (int i = 0; i < 8; i++) {
            float q = truncf(z[i] * 0.25f);
            float mres = fmaf(-4.f, q, z[i]);
            bq[m][i] = cround1(mres);
        }
#pragma unroll
        for (int i = 0; i < 8; i++) xl[i] = cp[i] * 0.25f;
    }

    // ------------------------------ decode --------------------------------
    float xh[8] = {0.f, 0.f, 0.f, 0.f, 0.f, 0.f, 0.f, 0.f};
    float scale = 1.f;
#pragma unroll
    for (int m = 0; m < 3; m++) {
        const float* b = bq[m];
        // Gb = b @ G.T : G.T == 'rows' which is sparse (<=3 nonzeros/column)
        float Gb[8];
        Gb[0] = fmaf(0.5f, b[7], fmaf(2.f, b[0], -b[1]));
#pragma unroll
        for (int j = 1; j < 6; j++) Gb[j] = fmaf(0.5f, b[7], b[j] - b[j + 1]);
        Gb[6] = fmaf(0.5f, b[7], b[6]);
        Gb[7] = 0.5f * b[7];

        float gq[8], cp[8];
#pragma unroll
        for (int i = 0; i < 8; i++) gq[i] = Gb[i] * 0.25f;
        closest_E8(gq, cp);

#pragma unroll
        for (int i = 0; i < 8; i++) {
            float xi = fmaf(-4.f, cp[i], Gb[i]);  // Gb - Q*closest(Gb/Q)
            xh[i] = fmaf(scale, xi, xh[i]);
        }
        scale *= 4.f;
    }

    float4 o0, o1;
    o0.x = beta * xh[0]; o0.y = beta * xh[1];
    o0.z = beta * xh[2]; o0.w = beta * xh[3];
    o1.x = beta * xh[4]; o1.y = beta * xh[5];
    o1.z = beta * xh[6]; o1.w = beta * xh[7];
    float4* out4 = reinterpret_cast<float4*>(out);
    out4[2 * r] = o0;
    out4[2 * r + 1] = o1;
}

extern "C" void kernel_launch(void* const* d_in, const int* in_sizes, int n_in,
                              void* d_out, int out_size) {
    // metadata order: x, beta, G, G_inv, eps  (G, G_inv unused: structure hardcoded)
    const float* x = (const float*)d_in[0];
    const float* beta = (const float*)d_in[1];
    const float* eps = (const float*)d_in[4];
    float* out = (float*)d_out;

    int N = in_sizes[0] / 8;
    int threads = 256;
    int blocks = (N + threads - 1) / threads;
    LatticeQuantizer_kernel<<<blocks, threads>>>(x, beta, eps, out, N);
}

// round 3
// speedup vs baseline: 1.6270x; 1.6270x over previous
#include <cuda_runtime.h>

#define TINYF 1.1920928955078125e-07f  // np.finfo(float32).eps

__device__ __forceinline__ float cround1(float x) {
    // floor(x - sign(x)*tiny + 0.5); copysign matches sign() for all x incl. +-0 here
    float s = copysignf(TINYF, x);
    return floorf((x - s) + 0.5f);
}

// One coset step of the D8 closest-point algorithm:
// f = round(x); if sum(f) odd, flip the coordinate with max |x - f|
// using the reference's exact tie rules. Writes candidate y.
__device__ __forceinline__ void coset_flip(const float xv[8], float y[8]) {
    float f[8], e[8];
#pragma unroll
    for (int i = 0; i < 8; i++) {
        f[i] = cround1(xv[i]);
        e[i] = xv[i] - f[i];
    }
    float sum = ((f[0] + f[1]) + (f[2] + f[3])) + ((f[4] + f[5]) + (f[6] + f[7]));
    int odd = ((int)sum) & 1;  // sum is an exact small integer

    // first-index argmax of |e| (strict > keeps the first max, like jnp.argmax)
    float bd = fabsf(e[0]);
    float be = e[0];
    float bx = xv[0];
    int bk = 0;
#pragma unroll
    for (int i = 1; i < 8; i++) {
        float di = fabsf(e[i]);
        bool g = di > bd;
        bd = g ? di : bd;
        be = g ? e[i] : be;
        bx = g ? xv[i] : bx;
        bk = g ? i : bk;
    }
    // step = where(xk>=0, where(fk<xk,1,-1), where(fk<=xk,1,-1));
    // fk<xk <=> e>0, fk<=xk <=> e>=0
    float step = (bx >= 0.f) ? ((be > 0.f) ? 1.f : -1.f)
                             : ((be >= 0.f) ? 1.f : -1.f);
    int kk = odd ? bk : 8;  // 8 = no flip
#pragma unroll
    for (int i = 0; i < 8; i++)
        y[i] = (i == kk) ? (f[i] + step) : f[i];
}

// E8 = D8  U  (D8 + 1/2)
__device__ __forceinline__ void closest_E8(const float xv[8], float y[8]) {
    float y0[8], y1[8], xs[8];
    coset_flip(xv, y0);
#pragma unroll
    for (int i = 0; i < 8; i++) xs[i] = xv[i] - 0.5f;
    coset_flip(xs, y1);
#pragma unroll
    for (int i = 0; i < 8; i++) y1[i] += 0.5f;

    float d0 = 0.f, d1 = 0.f;
#pragma unroll
    for (int i = 0; i < 8; i++) {
        float t0 = xv[i] - y0[i];
        d0 = fmaf(t0, t0, d0);
        float t1 = xv[i] - y1[i];
        d1 = fmaf(t1, t1, d1);
    }
    bool c = d0 < d1;  // ties pick y1, matching jnp.where(d0 < d1, y0, y1)
#pragma unroll
    for (int i = 0; i < 8; i++) y[i] = c ? y0[i] : y1[i];
}

__global__ __launch_bounds__(256, 2)
void LatticeQuantizer_kernel(const float* __restrict__ x,
                             const float* __restrict__ betap,
                             const float* __restrict__ epsp,
                             float* __restrict__ out, int N) {
    int r = blockIdx.x * blockDim.x + threadIdx.x;
    if (r >= N) return;

    const float4* x4 = reinterpret_cast<const float4*>(x);
    float4 a = x4[2 * r];
    float4 bb = x4[2 * r + 1];

    float beta = __ldg(betap);
    float ib = 1.0f / beta;  // beta == 1 in this problem -> exact

    float4 e0 = __ldg(reinterpret_cast<const float4*>(epsp));
    float4 e1 = __ldg(reinterpret_cast<const float4*>(epsp) + 1);
    float ep[8] = {e0.x, e0.y, e0.z, e0.w, e1.x, e1.y, e1.z, e1.w};

    float xl[8] = {a.x * ib, a.y * ib, a.z * ib, a.w * ib,
                   bb.x * ib, bb.y * ib, bb.z * ib, bb.w * ib};

    // ------------------- encode: M=3 hierarchical layers -------------------
    float bq[3][8];
#pragma unroll
    for (int m = 0; m < 3; m++) {
        float tin[8], cp[8];
#pragma unroll
        for (int i = 0; i < 8; i++) tin[i] = xl[i] + ep[i];
        closest_E8(tin, cp);

        // z = cp @ G_inv  via exact forward solve against sparse 'rows'
        float z[8];
        z[0] = 0.5f * cp[0];
#pragma unroll
        for (int i = 1; i < 7; i++) z[i] = cp[i] + z[i - 1];
        float s06 = ((z[0] + z[1]) + (z[2] + z[3])) + ((z[4] + z[5]) + z[6]);
        z[7] = fmaf(2.f, cp[7], -s06);

        // b = custom_round(fmod(z, 4))  (exact dyadic decomposition of fmod)
#pragma unroll
        for (int i = 0; i < 8; i++) {
            float q = truncf(z[i] * 0.25f);
            float mres = fmaf(-4.f, q, z[i]);
            bq[m][i] = cround1(mres);
        }
#pragma unroll
        for (int i = 0; i < 8; i++) xl[i] = cp[i] * 0.25f;
    }

    // ------------------------------ decode --------------------------------
    float xh[8] = {0.f, 0.f, 0.f, 0.f, 0.f, 0.f, 0.f, 0.f};
    float scale = 1.f;
#pragma unroll
    for (int m = 0; m < 3; m++) {
        const float* b = bq[m];
        // Gb = b @ G.T : G.T == 'rows' which is sparse (<=3 nonzeros/column)
        float Gb[8];
        Gb[0] = fmaf(0.5f, b[7], fmaf(2.f, b[0], -b[1]));
#pragma unroll
        for (int j = 1; j < 6; j++) Gb[j] = fmaf(0.5f, b[7], b[j] - b[j + 1]);
        Gb[6] = fmaf(0.5f, b[7], b[6]);
        Gb[7] = 0.5f * b[7];

        float gq[8], cp[8];
#pragma unroll
        for (int i = 0; i < 8; i++) gq[i] = Gb[i] * 0.25f;
        closest_E8(gq, cp);

#pragma unroll
        for (int i = 0; i < 8; i++) {
            float xi = fmaf(-4.f, cp[i], Gb[i]);  // Gb - Q*closest(Gb/Q)
            xh[i] = fmaf(scale, xi, xh[i]);
        }
        scale *= 4.f;
    }

    float4 o0, o1;
    o0.x = beta * xh[0]; o0.y = beta * xh[1];
    o0.z = beta * xh[2]; o0.w = beta * xh[3];
    o1.x = beta * xh[4]; o1.y = beta * xh[5];
    o1.z = beta * xh[6]; o1.w = beta * xh[7];
    float4* out4 = reinterpret_cast<float4*>(out);
    out4[2 * r] = o0;
    out4[2 * r + 1] = o1;
}

extern "C" void kernel_launch(void* const* d_in, const int* in_sizes, int n_in,
                              void* d_out, int out_size) {
    // metadata order: x, beta, G, G_inv, eps  (G, G_inv unused: structure hardcoded)
    const float* x = (const float*)d_in[0];
    const float* beta = (const float*)d_in[1];
    const float* eps = (const float*)d_in[4];
    float* out = (float*)d_out;

    int N = in_sizes[0] / 8;
    int threads = 256;
    int blocks = (N + threads - 1) / threads;
    LatticeQuantizer_kernel<<<blocks, threads>>>(x, beta, eps, out, N);
}

// round 7
// speedup vs baseline: 2.2776x; 1.3999x over previous
#include <cuda_runtime.h>
#include <cstdint>

// custom_round: floor((x - copysign(tiny,x)) + 0.5), tiny = 2^-23,
// bit-identical to the reference for all inputs seen here.
__device__ __forceinline__ float cround1(float x) {
    uint32_t xb = __float_as_uint(x);
    // s = copysign(2^-23, x); compute x - s as x + (-s)
    float ns = __uint_as_float(((xb & 0x80000000u) ^ 0x80000000u) | 0x34000000u);
    return floorf((x + ns) + 0.5f);
}

struct CosetR {
    float d;     // squared distance of this coset's candidate (incl. flip fix)
    float step;  // flip direction
    int   kk;    // coord to flip; 8 = parity even, no flip
};

// One D8 coset: rounds into f[], returns distance/flip info without
// materializing the flipped vector.
__device__ __forceinline__ CosetR coset_eval(const float xv[8], float f[8]) {
    float e[8];
#pragma unroll
    for (int i = 0; i < 8; i++) {
        float xi = xv[i];
        uint32_t xb = __float_as_uint(xi);
        // sp = -copysign(2^-23, xi)
        float sp = __uint_as_float(((xb & 0x80000000u) ^ 0x80000000u) | 0x34000000u);
        float t = (xi + sp) + 0.5f;
        f[i] = floorf(t);
        e[i] = xi - f[i];                 // exact
    }
    float fsum = ((f[0] + f[1]) + (f[2] + f[3])) + ((f[4] + f[5]) + (f[6] + f[7]));
    int odd = ((int)fsum) & 1;            // fsum is an exact small integer

    float d = 0.f;
#pragma unroll
    for (int i = 0; i < 8; i++) d = fmaf(e[i], e[i], d);

    // Tournament argmax of |e|, leftmost wins ties (== jnp.argmax).
    bool c01 = fabsf(e[1]) > fabsf(e[0]);
    float b01 = c01 ? e[1] : e[0];  int k01 = c01 ? 1 : 0;
    bool c23 = fabsf(e[3]) > fabsf(e[2]);
    float b23 = c23 ? e[3] : e[2];  int k23 = c23 ? 3 : 2;
    bool c45 = fabsf(e[5]) > fabsf(e[4]);
    float b45 = c45 ? e[5] : e[4];  int k45 = c45 ? 5 : 4;
    bool c67 = fabsf(e[7]) > fabsf(e[6]);
    float b67 = c67 ? e[7] : e[6];  int k67 = c67 ? 7 : 6;
    bool ca = fabsf(b23) > fabsf(b01);
    float ba = ca ? b23 : b01;      int ka = ca ? k23 : k01;
    bool cb = fabsf(b67) > fabsf(b45);
    float bb = cb ? b67 : b45;      int kb = cb ? k67 : k45;
    bool cf = fabsf(bb) > fabsf(ba);
    float be = cf ? bb : ba;        int k  = cf ? kb : ka;

    // step: sign(be); if be==0 (=> all e==0 => k==0, x0==f0) use -sign(f0).
    // f is never -0.0 here, so the sign-bit test on f[0] is safe.
    float sgn   = __uint_as_float((__float_as_uint(be)   & 0x80000000u) | 0x3f800000u);
    float zstep = __uint_as_float(((__float_as_uint(f[0]) & 0x80000000u) ^ 0x80000000u) | 0x3f800000u);
    float step = (be == 0.f) ? zstep : sgn;

    // flipped distance = d - be^2 + (be-step)^2 = d + 1 - 2*|be| (step=sgn(be) if be!=0)
    float adj = fmaf(-2.f, fabsf(be), 1.f);

    CosetR r;
    r.kk   = odd ? k : 8;
    r.d    = odd ? (d + adj) : d;
    r.step = step;
    return r;
}

// E8 = D8 U (D8 + 1/2); ties (d0==d1) pick coset 1, matching reference.
__device__ __forceinline__ void closest_E8(const float x[8], float y[8]) {
    float f0[8], f1[8], xs[8];
    CosetR c0 = coset_eval(x, f0);
#pragma unroll
    for (int i = 0; i < 8; i++) xs[i] = x[i] - 0.5f;
    CosetR c1 = coset_eval(xs, f1);

    bool pick0 = c0.d < c1.d;
    int   kk = pick0 ? c0.kk : c1.kk;
    float st = pick0 ? c0.step : c1.step;
    float hb = pick0 ? 0.f : 0.5f;
#pragma unroll
    for (int i = 0; i < 8; i++) {
        float yi = (pick0 ? f0[i] : f1[i]) + hb;   // exact (integer + 0.5)
        if (i == kk) yi += st;                     // exact dyadic add
        y[i] = yi;
    }
}

__global__ __launch_bounds__(256, 3)
void LatticeQuantizer_kernel(const float* __restrict__ x,
                             const float* __restrict__ betap,
                             const float* __restrict__ epsp,
                             float* __restrict__ out, int N) {
    int r = blockIdx.x * blockDim.x + threadIdx.x;
    if (r >= N) return;

    const float4* x4 = reinterpret_cast<const float4*>(x);
    float4 a  = x4[2 * r];
    float4 bv = x4[2 * r + 1];

    float beta = __ldg(betap);
    float ib = 1.0f / beta;                      // beta == 1 -> exact

    float4 e0 = __ldg(reinterpret_cast<const float4*>(epsp));
    float4 e1 = __ldg(reinterpret_cast<const float4*>(epsp) + 1);
    float ep[8] = {e0.x, e0.y, e0.z, e0.w, e1.x, e1.y, e1.z, e1.w};

    // layer-0 input: x/beta + eps
    float cur[8] = {a.x * ib + ep[0], a.y * ib + ep[1],
                    a.z * ib + ep[2], a.w * ib + ep[3],
                    bv.x * ib + ep[4], bv.y * ib + ep[5],
                    bv.z * ib + ep[6], bv.w * ib + ep[7]};

    float xh[8] = {0.f, 0.f, 0.f, 0.f, 0.f, 0.f, 0.f, 0.f};
    float scale = 1.f;

#pragma unroll
    for (int m = 0; m < 3; m++) {
        // ---------------- encode layer m ----------------
        float cp[8];
        closest_E8(cur, cp);

        // z = cp @ G_inv via exact forward solve (rows * z = cp).
        // NOTE: z is a QUARTER-integer when cp is in the half coset, so the
        // custom_round after fmod is REQUIRED (snaps .25/.75 like reference).
        float z[8];
        z[0] = 0.5f * cp[0];
#pragma unroll
        for (int i = 1; i < 7; i++) z[i] = cp[i] + z[i - 1];
        float s06 = ((z[0] + z[1]) + (z[2] + z[3])) + ((z[4] + z[5]) + z[6]);
        z[7] = fmaf(2.f, cp[7], -s06);

        // b = custom_round(fmod(z, 4)) — exact dyadic decomposition of fmod
        float b[8];
#pragma unroll
        for (int i = 0; i < 8; i++) {
            float q = truncf(z[i] * 0.25f);        // z*0.25 exact (1/16 grid)
            float mres = fmaf(-4.f, q, z[i]);      // exact, quarter-integer in (-4,4)
            b[i] = cround1(mres);
        }

        if (m < 2) {
#pragma unroll
            for (int i = 0; i < 8; i++)
                cur[i] = fmaf(cp[i], 0.25f, ep[i]);  // cp*0.25 exact -> single round
        }

        // ---------------- decode layer m (fused) ----------------
        // Gb = b @ G.T (G.T == sparse 'rows')
        float Gb[8];
        Gb[0] = fmaf(0.5f, b[7], fmaf(2.f, b[0], -b[1]));
#pragma unroll
        for (int j = 1; j < 6; j++) Gb[j] = fmaf(0.5f, b[7], b[j] - b[j + 1]);
        Gb[6] = fmaf(0.5f, b[7], b[6]);
        Gb[7] = 0.5f * b[7];

        float gq[8], cq[8];
#pragma unroll
        for (int i = 0; i < 8; i++) gq[i] = Gb[i] * 0.25f;   // exact (1/8 grid)
        closest_E8(gq, cq);

#pragma unroll
        for (int i = 0; i < 8; i++) {
            float xi = fmaf(-4.f, cq[i], Gb[i]);             // exact
            xh[i] = fmaf(scale, xi, xh[i]);                  // exact dyadic
        }
        scale *= 4.f;
    }

    float4 o0, o1;
    o0.x = beta * xh[0]; o0.y = beta * xh[1];
    o0.z = beta * xh[2]; o0.w = beta * xh[3];
    o1.x = beta * xh[4]; o1.y = beta * xh[5];
    o1.z = beta * xh[6]; o1.w = beta * xh[7];
    float4* out4 = reinterpret_cast<float4*>(out);
    out4[2 * r]     = o0;
    out4[2 * r + 1] = o1;
}

extern "C" void kernel_launch(void* const* d_in, const int* in_sizes, int n_in,
                              void* d_out, int out_size) {
    // metadata order: x, beta, G, G_inv, eps (G/G_inv structure hardcoded)
    const float* x    = (const float*)d_in[0];
    const float* beta = (const float*)d_in[1];
    const float* eps  = (const float*)d_in[4];
    float* out = (float*)d_out;

    int N = in_sizes[0] / 8;
    int threads = 256;
    int blocks = (N + threads - 1) / threads;
    LatticeQuantizer_kernel<<<blocks, threads>>>(x, beta, eps, out, N);
}